// round 1
// baseline (speedup 1.0000x reference)
#include <cuda_runtime.h>

#define SDIM 8192
#define NTHREADS 1024
#define PER_T (SDIM / NTHREADS)   // 8

__device__ __forceinline__ float softplus_f(float x) {
    // matches jax.nn.softplus = logaddexp(x, 0) = max(x,0) + log1p(exp(-|x|))
    return fmaxf(x, 0.0f) + log1pf(expf(-fabsf(x)));
}

// padded smem index: conflict-free for both strided (phase1) and
// contiguous-per-thread (phase2) access patterns
__device__ __forceinline__ int pidx(int s) { return s + (s >> 3); }

__global__ void __launch_bounds__(NTHREADS, 1)
soc_kernel(const float4* __restrict__ X, const float* __restrict__ SC,
           const float* __restrict__ W1, const float* __restrict__ b1,
           const float* __restrict__ W2, const float* __restrict__ b2,
           const float* __restrict__ Wa, const float* __restrict__ ba,
           const float* __restrict__ Wb, const float* __restrict__ bb,
           float* __restrict__ out)
{
    __shared__ float sdelta[SDIM + SDIM / 8];   // 36 KB padded scan buffer
    __shared__ float swtot[32];
    __shared__ float s_init;

    const int b   = blockIdx.x;
    const int tid = threadIdx.x;
    const float4* Xb   = X + (size_t)b * SDIM;
    float*        outb = out + (size_t)b * SDIM;

    // per-batch scalars
    const float Q    = SC[b * 4 + 0];
    const float eta0 = SC[b * 4 + 1];
    const float wa0 = Wa[0], wa1 = Wa[1], vba = ba[0];
    const float vwb = Wb[0], vbb = bb[0];
    const float scale = eta0 / (3600.0f * Q);

    if (tid == 0) {
        // SOC_init from the first timestep's features + SC
        float4 x0 = Xb[0];
        const float R = SC[b * 4 + 2], sc3 = SC[b * 4 + 3];
        float h   = softplus_f(x0.y * W1[0] + x0.z * W1[1] + x0.w * W1[2]
                               + R * W1[3] + b1[0]);
        float raw = h * W2[0] + b2[0];
        s_init = sc3 * (1.0f + raw);
    }

    // ---- Phase 1: coalesced loads, compute delta_SOC[s] into smem ----
    #pragma unroll
    for (int k = 0; k < PER_T; k++) {
        int s = tid + k * NTHREADS;
        float4 x = Xb[s];
        float d = 0.0f;
        if (s < SDIM - 1) {
            float tn   = ((const float*)Xb)[(size_t)(s + 1) * 4];  // times[s+1], L1 hit
            float de   = softplus_f(x.y * wa0 + x.z * wa1 + vba) * vwb + vbb;
            float rate = scale * (1.0f + de) * x.y;                // x.y == I
            d = rate * (tn - x.x);                                 // dt = t[s+1]-t[s]
        }
        sdelta[pidx(s)] = d;
    }
    __syncthreads();

    // ---- Phase 2: block-wide inclusive scan of delta ----
    float loc[PER_T];
    float run = 0.0f;
    // base = tid*8 is 8-aligned, so pidx(base+i) == tid*9 + i (stride 9: bank-conflict-free)
    #pragma unroll
    for (int i = 0; i < PER_T; i++) {
        run += sdelta[tid * 9 + i];
        loc[i] = run;
    }
    const int lane = tid & 31, warp = tid >> 5;
    float v = run;
    #pragma unroll
    for (int off = 1; off < 32; off <<= 1) {
        float u = __shfl_up_sync(0xffffffffu, v, off);
        if (lane >= off) v += u;
    }
    if (lane == 31) swtot[warp] = v;
    __syncthreads();
    if (warp == 0) {
        float wv = swtot[lane];
        #pragma unroll
        for (int off = 1; off < 32; off <<= 1) {
            float u = __shfl_up_sync(0xffffffffu, wv, off);
            if (lane >= off) wv += u;
        }
        swtot[lane] = wv;   // inclusive warp-total scan
    }
    __syncthreads();
    const float warp_excl   = (warp > 0) ? swtot[warp - 1] : 0.0f;
    const float thread_excl = warp_excl + (v - run);
    #pragma unroll
    for (int i = 0; i < PER_T; i++) {
        sdelta[tid * 9 + i] = thread_excl + loc[i];   // inclusive prefix P[s]
    }
    __syncthreads();

    // ---- Phase 3: coalesced stores: out[s] = SOC_init + P[s-1] ----
    const float soc0 = s_init;
    #pragma unroll
    for (int k = 0; k < PER_T; k++) {
        int s = tid + k * NTHREADS;
        float p = (s == 0) ? 0.0f : sdelta[pidx(s - 1)];
        outb[s] = soc0 + p;
    }
}

extern "C" void kernel_launch(void* const* d_in, const int* in_sizes, int n_in,
                              void* d_out, int out_size)
{
    (void)in_sizes; (void)n_in; (void)out_size;
    const float4* X  = (const float4*)d_in[0];
    const float*  SC = (const float*)d_in[1];
    const float*  W1 = (const float*)d_in[2];
    const float*  b1 = (const float*)d_in[3];
    const float*  W2 = (const float*)d_in[4];
    const float*  b2 = (const float*)d_in[5];
    const float*  Wa = (const float*)d_in[6];
    const float*  ba = (const float*)d_in[7];
    const float*  Wb = (const float*)d_in[8];
    const float*  bb = (const float*)d_in[9];
    float* out = (float*)d_out;

    soc_kernel<<<2048, NTHREADS>>>(X, SC, W1, b1, W2, b2, Wa, ba, Wb, bb, out);
}

// round 2
// speedup vs baseline: 1.1343x; 1.1343x over previous
#include <cuda_runtime.h>

#define SDIM 8192
#define NTHREADS 1024
#define PER_T (SDIM / NTHREADS)   // 8

__device__ __forceinline__ float softplus_f(float x) {
    // matches jax.nn.softplus = max(x,0) + log1p(exp(-|x|))
    return fmaxf(x, 0.0f) + log1pf(expf(-fabsf(x)));
}

// pad one word per 32: conflict-free for both the strided phase-1 write
// (consecutive addresses within a warp) and the contiguous phase-2 read
// (lane l reads base 8l + l/4 -> banks q+8r, all distinct)
__device__ __forceinline__ int pidx(int s) { return s + (s >> 5); }

__global__ void __launch_bounds__(NTHREADS, 2)
soc_kernel(const float4* __restrict__ X, const float* __restrict__ SC,
           const float* __restrict__ W1, const float* __restrict__ b1,
           const float* __restrict__ W2, const float* __restrict__ b2,
           const float* __restrict__ Wa, const float* __restrict__ ba,
           const float* __restrict__ Wb, const float* __restrict__ bb,
           float* __restrict__ out)
{
    __shared__ float sdelta[SDIM + SDIM / 32];   // 33 KB padded scan buffer
    __shared__ float swtot[32];
    __shared__ float s_init;

    const int b   = blockIdx.x;
    const int tid = threadIdx.x;
    const float4* Xb   = X + (size_t)b * SDIM;
    float*        outb = out + (size_t)b * SDIM;

    // per-batch scalars
    const float Q    = SC[b * 4 + 0];
    const float eta0 = SC[b * 4 + 1];
    const float wa0 = Wa[0], wa1 = Wa[1], vba = ba[0];
    const float vwb = Wb[0], vbb = bb[0];
    const float scale = eta0 / (3600.0f * Q);

    if (tid == 0) {
        // SOC_init from the first timestep's features + SC
        float4 x0 = Xb[0];
        const float R = SC[b * 4 + 2], sc3 = SC[b * 4 + 3];
        float h   = softplus_f(x0.y * W1[0] + x0.z * W1[1] + x0.w * W1[2]
                               + R * W1[3] + b1[0]);
        float raw = h * W2[0] + b2[0];
        s_init = sc3 * (1.0f + raw);
    }

    // ---- Phase 1: coalesced loads, compute delta_SOC[s] into smem ----
    #pragma unroll
    for (int k = 0; k < PER_T; k++) {
        int s = tid + k * NTHREADS;
        float4 x = Xb[s];
        float d = 0.0f;
        if (s < SDIM - 1) {
            float tn   = ((const float*)Xb)[(size_t)(s + 1) * 4];  // times[s+1], L1 hit
            float de   = softplus_f(x.y * wa0 + x.z * wa1 + vba) * vwb + vbb;
            float rate = scale * (1.0f + de) * x.y;                // x.y == I
            d = rate * (tn - x.x);                                 // dt = t[s+1]-t[s]
        }
        sdelta[pidx(s)] = d;
    }
    __syncthreads();

    // ---- Phase 2: block-wide inclusive scan of delta ----
    float loc[PER_T];
    float run = 0.0f;
    const int rbase = pidx(tid * PER_T);   // contiguous 8 words (no pad crossing)
    #pragma unroll
    for (int i = 0; i < PER_T; i++) {
        run += sdelta[rbase + i];
        loc[i] = run;
    }
    const int lane = tid & 31, warp = tid >> 5;
    float v = run;
    #pragma unroll
    for (int off = 1; off < 32; off <<= 1) {
        float u = __shfl_up_sync(0xffffffffu, v, off);
        if (lane >= off) v += u;
    }
    if (lane == 31) swtot[warp] = v;
    __syncthreads();
    if (warp == 0) {
        float wv = swtot[lane];
        #pragma unroll
        for (int off = 1; off < 32; off <<= 1) {
            float u = __shfl_up_sync(0xffffffffu, wv, off);
            if (lane >= off) wv += u;
        }
        swtot[lane] = wv;   // inclusive warp-total scan
    }
    __syncthreads();
    const float warp_excl   = (warp > 0) ? swtot[warp - 1] : 0.0f;
    const float thread_excl = warp_excl + (v - run);   // sum of deltas [0, tid*8)

    // ---- Phase 3 (fused): out[s] = soc0 + P[s-1], directly from registers.
    // Thread tid owns s = tid*8 .. tid*8+7 (contiguous): 2x STG.128.
    const float soc0 = s_init;
    float4 o0, o1;
    o0.x = soc0 + thread_excl;            // i=0: P[s-1] = exclusive prefix
    o0.y = soc0 + thread_excl + loc[0];
    o0.z = soc0 + thread_excl + loc[1];
    o0.w = soc0 + thread_excl + loc[2];
    o1.x = soc0 + thread_excl + loc[3];
    o1.y = soc0 + thread_excl + loc[4];
    o1.z = soc0 + thread_excl + loc[5];
    o1.w = soc0 + thread_excl + loc[6];
    float4* outv = (float4*)(outb + tid * PER_T);
    outv[0] = o0;
    outv[1] = o1;
}

extern "C" void kernel_launch(void* const* d_in, const int* in_sizes, int n_in,
                              void* d_out, int out_size)
{
    (void)in_sizes; (void)n_in; (void)out_size;
    const float4* X  = (const float4*)d_in[0];
    const float*  SC = (const float*)d_in[1];
    const float*  W1 = (const float*)d_in[2];
    const float*  b1 = (const float*)d_in[3];
    const float*  W2 = (const float*)d_in[4];
    const float*  b2 = (const float*)d_in[5];
    const float*  Wa = (const float*)d_in[6];
    const float*  ba = (const float*)d_in[7];
    const float*  Wb = (const float*)d_in[8];
    const float*  bb = (const float*)d_in[9];
    float* out = (float*)d_out;

    soc_kernel<<<2048, NTHREADS>>>(X, SC, W1, b1, W2, b2, Wa, ba, Wb, bb, out);
}